// round 5
// baseline (speedup 1.0000x reference)
#include <cuda_runtime.h>
#include <cstdint>

// ---------------------------------------------------------------------------
// SelfAttention: out = softmax((xWq^T+bq)(xWk^T+bk)^T / sqrt(D)) (xWv^T+bv)
// B=4, S=2048, D=1024. fp32 I/O.
// Round 4: 3-stage cp.async pipeline, 2 CTAs/SM, coalesced V transpose kernel
// (replaces scalar transposed epilogue). TF32 mma.sync, operands pre-rounded.
// ---------------------------------------------------------------------------

#define DEV_INLINE __device__ __forceinline__

static constexpr int Bsz = 4;
static constexpr int S   = 2048;
static constexpr int D   = 1024;
static constexpr int MQK = Bsz * S;

// Scratch (static __device__ arrays: allocation-free per harness rules)
__device__ float g_q [(size_t)MQK * D];
__device__ float g_k [(size_t)MQK * D];
__device__ float g_v [(size_t)MQK * D];
__device__ float g_vT[(size_t)Bsz * D * S];   // V transposed per batch
__device__ float g_s [(size_t)Bsz * S * S];   // scores; prologue aliases
                                              // rounded x / W copies here

DEV_INLINE float tf32_round(float x) {
    uint32_t u;
    asm("cvt.rna.tf32.f32 %0, %1;" : "=r"(u) : "f"(x));
    return __uint_as_float(u);
}

DEV_INLINE uint32_t smem_u32(const void* p) {
    uint32_t a;
    asm("{ .reg .u64 t; cvta.to.shared.u64 t, %1; cvt.u32.u64 %0, t; }"
        : "=r"(a) : "l"(p));
    return a;
}

DEV_INLINE void cp_async16(uint32_t dst, const void* src) {
    asm volatile("cp.async.cg.shared.global [%0], [%1], 16;"
                 :: "r"(dst), "l"(src) : "memory");
}
DEV_INLINE void cp_commit() {
    asm volatile("cp.async.commit_group;" ::: "memory");
}
template <int N> DEV_INLINE void cp_wait() {
    asm volatile("cp.async.wait_group %0;" :: "n"(N) : "memory");
}

DEV_INLINE void mma_16x8x8(float acc[4], const uint32_t a[4], const uint32_t b[2]) {
    asm volatile(
        "mma.sync.aligned.m16n8k8.row.col.f32.tf32.tf32.f32 "
        "{%0,%1,%2,%3}, {%4,%5,%6,%7}, {%8,%9}, {%0,%1,%2,%3};\n"
        : "+f"(acc[0]), "+f"(acc[1]), "+f"(acc[2]), "+f"(acc[3])
        : "r"(a[0]), "r"(a[1]), "r"(a[2]), "r"(a[3]),
          "r"(b[0]), "r"(b[1]));
}

// ---------------------------------------------------------------------------
// Elementwise tf32 rounding copy (prep pass for x and the weights)
// ---------------------------------------------------------------------------
__global__ void __launch_bounds__(256)
round_copy_kernel(const float* __restrict__ src, float* __restrict__ dst, int n4)
{
    const int i = blockIdx.x * 256 + threadIdx.x;
    if (i < n4) {
        float4 v = reinterpret_cast<const float4*>(src)[i];
        v.x = tf32_round(v.x); v.y = tf32_round(v.y);
        v.z = tf32_round(v.z); v.w = tf32_round(v.w);
        reinterpret_cast<float4*>(dst)[i] = v;
    }
}

// ---------------------------------------------------------------------------
// 32x32 smem-tiled transpose (per batch z): out[d][s] = in[s][d]
// in: [S, D] row-major (+ batch stride), out: [D, S] row-major (+ batch stride)
// ---------------------------------------------------------------------------
__global__ void __launch_bounds__(256)
transpose_kernel(const float* __restrict__ in, float* __restrict__ out)
{
    __shared__ float t[32][33];
    const int s0 = blockIdx.x * 32;
    const int d0 = blockIdx.y * 32;
    const int bz = blockIdx.z;
    in  += (size_t)bz * S * D;
    out += (size_t)bz * D * S;

    const int tx = threadIdx.x & 31;
    const int ty = threadIdx.x >> 5;      // 0..7
    #pragma unroll
    for (int j = 0; j < 4; j++)
        t[ty + 8 * j][tx] = in[(size_t)(s0 + ty + 8 * j) * D + d0 + tx];
    __syncthreads();
    #pragma unroll
    for (int j = 0; j < 4; j++)
        out[(size_t)(d0 + ty + 8 * j) * S + s0 + tx] = t[tx][ty + 8 * j];
}

// ---------------------------------------------------------------------------
// TF32 NT GEMM: C[m,n] = alpha * sum_k A[m,k]*B[n,k]  (+bias[n])
// A: [M,K] row-major, B: [N,K] row-major, both ALREADY tf32-valued in gmem.
// CTA 128x128x(BK=32), 128 threads = 4 warps of 64x64.
// 3-stage cp.async pipeline, 2 CTAs/SM. blockIdx.z batches.
// ROUND_OUT: round result to tf32 before store (feeds a later GEMM).
// ---------------------------------------------------------------------------
static constexpr int BM = 128, BN = 128, BK = 32;
static constexpr int ROWF   = BK + 4;            // 36 floats/row (16B-aligned)
static constexpr int STG    = BM * ROWF;         // floats per operand stage
static constexpr int STAGES = 3;
static constexpr int DYN_SMEM = STAGES * 2 * STG * 4;   // 110592 B

template <bool ROUND_OUT>
__global__ void __launch_bounds__(128, 2)
gemm_mma_kernel(const float* __restrict__ A, int lda, long long strideA,
                const float* __restrict__ B, int ldb, long long strideB,
                float* __restrict__ C, int ldc, long long strideC,
                const float* __restrict__ bias, int K, float alpha)
{
    extern __shared__ float dyn[];
    float* As = dyn;                    // [STAGES][STG]
    float* Bs = dyn + STAGES * STG;     // [STAGES][STG]
    const uint32_t sA = smem_u32(As);
    const uint32_t sB = smem_u32(Bs);

    const int tid  = threadIdx.x;
    const int wid  = tid >> 5;
    const int lane = tid & 31;
    const int m_w  = (wid & 1) * 64;          // 2 warps along M
    const int n_w  = (wid >> 1) * 64;         // 2 warps along N
    const int group = lane >> 2;              // 0..7
    const int tig   = lane & 3;               // 0..3

    const int bz = blockIdx.z;
    A += (size_t)bz * strideA;
    B += (size_t)bz * strideB;
    C += (size_t)bz * strideC;
    const int bm = blockIdx.y * BM;
    const int bn = blockIdx.x * BN;

    float acc[4][8][4];
    #pragma unroll
    for (int mi = 0; mi < 4; mi++)
        #pragma unroll
        for (int ni = 0; ni < 8; ni++)
            #pragma unroll
            for (int r = 0; r < 4; r++) acc[mi][ni][r] = 0.0f;

    // loader: 8 float4 per operand per thread (128 rows x 8 float4-cols)
    const int lr = tid >> 3;           // base row 0..15
    const int lc = tid & 7;            // float4 col 0..7
    auto load_stage = [&](int s, int k0) {
        const uint32_t offA = sA + (uint32_t)s * STG * 4;
        const uint32_t offB = sB + (uint32_t)s * STG * 4;
        #pragma unroll
        for (int i = 0; i < 8; i++) {
            const int r = lr + 16 * i;
            cp_async16(offA + (uint32_t)(r * ROWF + lc * 4) * 4,
                       &A[(size_t)(bm + r) * lda + k0 + lc * 4]);
        }
        #pragma unroll
        for (int i = 0; i < 8; i++) {
            const int r = lr + 16 * i;
            cp_async16(offB + (uint32_t)(r * ROWF + lc * 4) * 4,
                       &B[(size_t)(bn + r) * ldb + k0 + lc * 4]);
        }
        cp_commit();
    };

    const int nst = K / BK;
    load_stage(0, 0);
    load_stage(1 % STAGES, BK);        // nst >= 2 always here (K >= 1024)

    int buf = 0;
    for (int i = 0; i < nst; i++) {
        cp_wait<1>();
        __syncthreads();

        if (i + 2 < nst) {
            load_stage((i + 2) % STAGES, (i + 2) * BK);
        } else {
            cp_commit();               // keep group accounting uniform
        }

        const float* as = As + buf * STG;
        const float* bs = Bs + buf * STG;

        #pragma unroll
        for (int ks = 0; ks < BK; ks += 8) {
            uint32_t afr[4][4];
            #pragma unroll
            for (int mi = 0; mi < 4; mi++) {
                const int r = m_w + mi * 16;
                afr[mi][0] = __float_as_uint(as[(r + group    ) * ROWF + ks + tig    ]);
                afr[mi][1] = __float_as_uint(as[(r + group + 8) * ROWF + ks + tig    ]);
                afr[mi][2] = __float_as_uint(as[(r + group    ) * ROWF + ks + tig + 4]);
                afr[mi][3] = __float_as_uint(as[(r + group + 8) * ROWF + ks + tig + 4]);
            }
            uint32_t bfr[8][2];
            #pragma unroll
            for (int ni = 0; ni < 8; ni++) {
                const int c = n_w + ni * 8;
                bfr[ni][0] = __float_as_uint(bs[(c + group) * ROWF + ks + tig    ]);
                bfr[ni][1] = __float_as_uint(bs[(c + group) * ROWF + ks + tig + 4]);
            }
            #pragma unroll
            for (int mi = 0; mi < 4; mi++)
                #pragma unroll
                for (int ni = 0; ni < 8; ni++)
                    mma_16x8x8(acc[mi][ni], afr[mi], bfr[ni]);
        }
        __syncthreads();
        buf = (buf + 1 == STAGES) ? 0 : buf + 1;
    }

    // ---- epilogue: coalesced float2 stores ----
    #pragma unroll
    for (int mi = 0; mi < 4; mi++) {
        const int row0 = bm + m_w + mi * 16 + group;
        #pragma unroll
        for (int ni = 0; ni < 8; ni++) {
            const int col0 = bn + n_w + ni * 8 + tig * 2;
            float v00 = acc[mi][ni][0] * alpha;
            float v01 = acc[mi][ni][1] * alpha;
            float v10 = acc[mi][ni][2] * alpha;
            float v11 = acc[mi][ni][3] * alpha;
            if (bias) {
                const float b0 = bias[col0], b1 = bias[col0 + 1];
                v00 += b0; v01 += b1; v10 += b0; v11 += b1;
            }
            if (ROUND_OUT) {
                v00 = tf32_round(v00); v01 = tf32_round(v01);
                v10 = tf32_round(v10); v11 = tf32_round(v11);
            }
            *reinterpret_cast<float2*>(&C[(size_t)row0 * ldc + col0]) =
                make_float2(v00, v01);
            *reinterpret_cast<float2*>(&C[(size_t)(row0 + 8) * ldc + col0]) =
                make_float2(v10, v11);
        }
    }
}

// ---------------------------------------------------------------------------
// Row softmax, in place, output rounded to tf32 (feeds the PV GEMM).
// One block (256 threads) per row of 2048 floats.
// ---------------------------------------------------------------------------
__global__ void __launch_bounds__(256)
softmax_kernel(float* __restrict__ Smat, int ncols)
{
    float* p = Smat + (size_t)blockIdx.x * ncols;
    const int tid  = threadIdx.x;
    const int warp = tid >> 5;
    const int lane = tid & 31;

    __shared__ float red_max[8];
    __shared__ float red_sum[8];

    float v[8];
    float mx = -1e30f;
    #pragma unroll
    for (int i = 0; i < 8; i++) {
        v[i] = p[tid + 256 * i];
        mx = fmaxf(mx, v[i]);
    }
    #pragma unroll
    for (int o = 16; o > 0; o >>= 1)
        mx = fmaxf(mx, __shfl_xor_sync(0xffffffffu, mx, o));
    if (lane == 0) red_max[warp] = mx;
    __syncthreads();
    float m = red_max[0];
    #pragma unroll
    for (int w = 1; w < 8; w++) m = fmaxf(m, red_max[w]);

    float sum = 0.f;
    #pragma unroll
    for (int i = 0; i < 8; i++) {
        v[i] = __expf(v[i] - m);
        sum += v[i];
    }
    #pragma unroll
    for (int o = 16; o > 0; o >>= 1)
        sum += __shfl_xor_sync(0xffffffffu, sum, o);
    if (lane == 0) red_sum[warp] = sum;
    __syncthreads();
    float total = 0.f;
    #pragma unroll
    for (int w = 0; w < 8; w++) total += red_sum[w];

    const float inv = 1.0f / total;
    #pragma unroll
    for (int i = 0; i < 8; i++)
        p[tid + 256 * i] = tf32_round(v[i] * inv);
}

// ---------------------------------------------------------------------------
extern "C" void kernel_launch(void* const* d_in, const int* in_sizes, int n_in,
                              void* d_out, int out_size)
{
    const float* x  = (const float*)d_in[0];
    const float* Wq = (const float*)d_in[1];
    const float* bq = (const float*)d_in[2];
    const float* Wk = (const float*)d_in[3];
    const float* bk = (const float*)d_in[4];
    const float* Wv = (const float*)d_in[5];
    const float* bv = (const float*)d_in[6];
    float* out = (float*)d_out;

    float *gq, *gk, *gv, *gvT, *gs;
    cudaGetSymbolAddress((void**)&gq,  g_q);
    cudaGetSymbolAddress((void**)&gk,  g_k);
    cudaGetSymbolAddress((void**)&gv,  g_v);
    cudaGetSymbolAddress((void**)&gvT, g_vT);
    cudaGetSymbolAddress((void**)&gs,  g_s);

    // tf32-rounded copies of x and weights, aliased into g_s (not yet live;
    // g_s is first written by the scores GEMM, which runs after QKV).
    float* xr  = gs;                                   // 8192*1024
    float* wqr = gs + (size_t)MQK * D;                 // 1024*1024
    float* wkr = wqr + (size_t)D * D;
    float* wvr = wkr + (size_t)D * D;

    cudaFuncSetAttribute(gemm_mma_kernel<true>,
                         cudaFuncAttributeMaxDynamicSharedMemorySize, DYN_SMEM);
    cudaFuncSetAttribute(gemm_mma_kernel<false>,
                         cudaFuncAttributeMaxDynamicSharedMemorySize, DYN_SMEM);

    // 0) prep: round x, Wq, Wk, Wv to tf32 values in gmem
    {
        const int nx4 = MQK * D / 4, nw4 = D * D / 4;
        round_copy_kernel<<<(nx4 + 255) / 256, 256>>>(x,  xr,  nx4);
        round_copy_kernel<<<(nw4 + 255) / 256, 256>>>(Wq, wqr, nw4);
        round_copy_kernel<<<(nw4 + 255) / 256, 256>>>(Wk, wkr, nw4);
        round_copy_kernel<<<(nw4 + 255) / 256, 256>>>(Wv, wvr, nw4);
    }

    const dim3 blk(128);

    // 1) QKV projections: [8192,1024] = x @ W^T + b (NT). Outputs rounded.
    {
        const dim3 grid(D / BN, MQK / BM, 1);
        gemm_mma_kernel<true><<<grid, blk, DYN_SMEM>>>(
            xr, D, 0, wqr, D, 0, gq, D, 0, bq, D, 1.0f);
        gemm_mma_kernel<true><<<grid, blk, DYN_SMEM>>>(
            xr, D, 0, wkr, D, 0, gk, D, 0, bk, D, 1.0f);
        gemm_mma_kernel<true><<<grid, blk, DYN_SMEM>>>(
            xr, D, 0, wvr, D, 0, gv, D, 0, bv, D, 1.0f);
    }

    // 1b) transpose V per batch: g_vT[b][d][s] = g_v[b][s][d]
    {
        const dim3 tgrid(S / 32, D / 32, Bsz);
        transpose_kernel<<<tgrid, 256>>>(gv, gvT);
    }

    // 2) scores[b] = Q[b] @ K[b]^T * (1/sqrt(D))  (overwrites aliased prep data)
    {
        const dim3 grid(S / BN, S / BM, Bsz);
        gemm_mma_kernel<false><<<grid, blk, DYN_SMEM>>>(
            gq, D, (long long)S * D,
            gk, D, (long long)S * D,
            gs, S, (long long)S * S,
            nullptr, D, 0.03125f /* 1/sqrt(1024) */);
    }

    // 3) row softmax (tf32-rounded output)
    softmax_kernel<<<Bsz * S, 256>>>(gs, S);

    // 4) out[b] = P[b] @ V[b] = P[b] @ (vT[b])^T  (NT path)
    {
        const dim3 grid(D / BN, S / BM, Bsz);
        gemm_mma_kernel<false><<<grid, blk, DYN_SMEM>>>(
            gs,  S, (long long)S * S,
            gvT, S, (long long)D * S,
            out, D, (long long)S * D,
            nullptr, S, 1.0f);
    }
}

// round 6
// speedup vs baseline: 1.0568x; 1.0568x over previous
#include <cuda_runtime.h>
#include <cstdint>

// ---------------------------------------------------------------------------
// SelfAttention: out = softmax((xWq^T+bq)(xWk^T+bk)^T / sqrt(D)) (xWv^T+bv)
// B=4, S=2048, D=1024. fp32 I/O.
// Round 5: revert mainloop to the proven R3 2-stage config; fuse QKV into one
// [8192,3072] GEMM (contiguous Wqkv + concat bias built by a single prep
// kernel); tiled V transpose. TF32 mma.sync, operands pre-rounded in gmem.
// ---------------------------------------------------------------------------

#define DEV_INLINE __device__ __forceinline__

static constexpr int Bsz = 4;
static constexpr int S   = 2048;
static constexpr int D   = 1024;
static constexpr int MQK = Bsz * S;
static constexpr int N3  = 3 * D;             // 3072

// Scratch (static __device__ arrays: allocation-free per harness rules)
__device__ float g_qkv[(size_t)MQK * N3];     // fused QKV output (96MB)
__device__ float g_vT [(size_t)Bsz * D * S];  // V transposed per batch (32MB)
__device__ float g_s  [(size_t)Bsz * S * S];  // scores (64MB); prologue aliases
                                              // rounded x / Wqkv copies here
__device__ float g_b  [N3];                   // concat bias

DEV_INLINE float tf32_round(float x) {
    uint32_t u;
    asm("cvt.rna.tf32.f32 %0, %1;" : "=r"(u) : "f"(x));
    return __uint_as_float(u);
}

DEV_INLINE uint32_t smem_u32(const void* p) {
    uint32_t a;
    asm("{ .reg .u64 t; cvta.to.shared.u64 t, %1; cvt.u32.u64 %0, t; }"
        : "=r"(a) : "l"(p));
    return a;
}

DEV_INLINE void cp_async16(uint32_t dst, const void* src) {
    asm volatile("cp.async.cg.shared.global [%0], [%1], 16;"
                 :: "r"(dst), "l"(src) : "memory");
}
DEV_INLINE void cp_commit() {
    asm volatile("cp.async.commit_group;" ::: "memory");
}
template <int N> DEV_INLINE void cp_wait() {
    asm volatile("cp.async.wait_group %0;" :: "n"(N) : "memory");
}

DEV_INLINE void mma_16x8x8(float acc[4], const uint32_t a[4], const uint32_t b[2]) {
    asm volatile(
        "mma.sync.aligned.m16n8k8.row.col.f32.tf32.tf32.f32 "
        "{%0,%1,%2,%3}, {%4,%5,%6,%7}, {%8,%9}, {%0,%1,%2,%3};\n"
        : "+f"(acc[0]), "+f"(acc[1]), "+f"(acc[2]), "+f"(acc[3])
        : "r"(a[0]), "r"(a[1]), "r"(a[2]), "r"(a[3]),
          "r"(b[0]), "r"(b[1]));
}

// ---------------------------------------------------------------------------
// prep_kernel: one launch does everything the GEMMs need:
//   blocks [0, 8192)            : xr = tf32_round(x)          (2M float4)
//   blocks [8192, 8192+3072)    : wr[w] = tf32_round(W[w])    (1024 blocks each)
//   blocks [11264, 11267)       : br[w] = b[w]                (copy, no round)
// ---------------------------------------------------------------------------
static constexpr int PREP_XB = MQK * D / 4 / 256;        // 8192
static constexpr int PREP_WB = D * D / 4 / 256;          // 1024
static constexpr int PREP_BLOCKS = PREP_XB + 3 * PREP_WB + 3;

__global__ void __launch_bounds__(256)
prep_kernel(const float* __restrict__ x,
            const float* __restrict__ Wq, const float* __restrict__ Wk,
            const float* __restrict__ Wv,
            const float* __restrict__ bq, const float* __restrict__ bk,
            const float* __restrict__ bv,
            float* __restrict__ xr, float* __restrict__ wr,
            float* __restrict__ br)
{
    const int b = blockIdx.x;
    const int t = threadIdx.x;
    if (b < PREP_XB) {
        const int i = b * 256 + t;
        float4 v = reinterpret_cast<const float4*>(x)[i];
        v.x = tf32_round(v.x); v.y = tf32_round(v.y);
        v.z = tf32_round(v.z); v.w = tf32_round(v.w);
        reinterpret_cast<float4*>(xr)[i] = v;
    } else if (b < PREP_XB + 3 * PREP_WB) {
        const int wi = b - PREP_XB;
        const int w  = wi >> 10;                 // 0,1,2
        const int i  = (wi & 1023) * 256 + t;
        const float* src = (w == 0) ? Wq : (w == 1) ? Wk : Wv;
        float* dst = wr + (size_t)w * D * D;
        float4 v = reinterpret_cast<const float4*>(src)[i];
        v.x = tf32_round(v.x); v.y = tf32_round(v.y);
        v.z = tf32_round(v.z); v.w = tf32_round(v.w);
        reinterpret_cast<float4*>(dst)[i] = v;
    } else {
        const int w = b - PREP_XB - 3 * PREP_WB; // 0,1,2
        const float* src = (w == 0) ? bq : (w == 1) ? bk : bv;
        reinterpret_cast<float4*>(br + w * D)[t] =
            reinterpret_cast<const float4*>(src)[t];
    }
}

// ---------------------------------------------------------------------------
// V transpose: out[b][d][s] = qkv[b*S+s][2048 + d]
// 32x32 smem tiles, 256 threads.
// ---------------------------------------------------------------------------
__global__ void __launch_bounds__(256)
transpose_kernel(const float* __restrict__ qkv, float* __restrict__ out)
{
    __shared__ float t[32][33];
    const int s0 = blockIdx.x * 32;
    const int d0 = blockIdx.y * 32;
    const int bz = blockIdx.z;
    const float* in = qkv + (size_t)bz * S * N3 + 2 * D;   // V column block
    out += (size_t)bz * D * S;

    const int tx = threadIdx.x & 31;
    const int ty = threadIdx.x >> 5;      // 0..7
    #pragma unroll
    for (int j = 0; j < 4; j++)
        t[ty + 8 * j][tx] = in[(size_t)(s0 + ty + 8 * j) * N3 + d0 + tx];
    __syncthreads();
    #pragma unroll
    for (int j = 0; j < 4; j++)
        out[(size_t)(d0 + ty + 8 * j) * S + s0 + tx] = t[tx][ty + 8 * j];
}

// ---------------------------------------------------------------------------
// TF32 NT GEMM: C[m,n] = alpha * sum_k A[m,k]*B[n,k]  (+bias[n])
// A: [M,K] row-major, B: [N,K] row-major, both ALREADY tf32-valued in gmem.
// CTA 128x128x(BK=32), 128 threads = 4 warps of 64x64.
// 2-stage cp.async pipeline (proven R3 config). blockIdx.z batches.
// ROUND_OUT: round result to tf32 before store (feeds a later GEMM).
// ---------------------------------------------------------------------------
static constexpr int BM = 128, BN = 128, BK = 32;
static constexpr int ROWF  = BK + 4;             // 36 floats/row (16B-aligned)
static constexpr int STG   = BM * ROWF;          // floats per operand stage
static constexpr int DYN_SMEM = 4 * STG * 4;     // 2 stages x (A+B) = 73728 B

template <bool ROUND_OUT>
__global__ void __launch_bounds__(128)
gemm_mma_kernel(const float* __restrict__ A, int lda, long long strideA,
                const float* __restrict__ B, int ldb, long long strideB,
                float* __restrict__ C, int ldc, long long strideC,
                const float* __restrict__ bias, int K, float alpha)
{
    extern __shared__ float dyn[];
    float* As = dyn;                 // [2][STG]
    float* Bs = dyn + 2 * STG;       // [2][STG]
    const uint32_t sA = smem_u32(As);
    const uint32_t sB = smem_u32(Bs);

    const int tid  = threadIdx.x;
    const int wid  = tid >> 5;
    const int lane = tid & 31;
    const int m_w  = (wid & 1) * 64;          // 2 warps along M
    const int n_w  = (wid >> 1) * 64;         // 2 warps along N
    const int group = lane >> 2;              // 0..7
    const int tig   = lane & 3;               // 0..3

    const int bz = blockIdx.z;
    A += (size_t)bz * strideA;
    B += (size_t)bz * strideB;
    C += (size_t)bz * strideC;
    const int bm = blockIdx.y * BM;
    const int bn = blockIdx.x * BN;

    float acc[4][8][4];
    #pragma unroll
    for (int mi = 0; mi < 4; mi++)
        #pragma unroll
        for (int ni = 0; ni < 8; ni++)
            #pragma unroll
            for (int r = 0; r < 4; r++) acc[mi][ni][r] = 0.0f;

    // loader: 8 float4 per operand per thread (128 rows x 8 float4-cols)
    const int lr = tid >> 3;           // base row 0..15
    const int lc = tid & 7;            // float4 col 0..7
    auto load_stage = [&](int s, int k0) {
        const uint32_t offA = sA + (uint32_t)s * STG * 4;
        const uint32_t offB = sB + (uint32_t)s * STG * 4;
        #pragma unroll
        for (int i = 0; i < 8; i++) {
            const int r = lr + 16 * i;
            cp_async16(offA + (uint32_t)(r * ROWF + lc * 4) * 4,
                       &A[(size_t)(bm + r) * lda + k0 + lc * 4]);
        }
        #pragma unroll
        for (int i = 0; i < 8; i++) {
            const int r = lr + 16 * i;
            cp_async16(offB + (uint32_t)(r * ROWF + lc * 4) * 4,
                       &B[(size_t)(bn + r) * ldb + k0 + lc * 4]);
        }
        cp_commit();
    };

    const int nst = K / BK;
    load_stage(0, 0);

    for (int i = 0; i < nst; i++) {
        if (i + 1 < nst) {
            load_stage((i + 1) & 1, (i + 1) * BK);
            cp_wait<1>();
        } else {
            cp_wait<0>();
        }
        __syncthreads();

        const float* as = As + (i & 1) * STG;
        const float* bs = Bs + (i & 1) * STG;

        #pragma unroll
        for (int ks = 0; ks < BK; ks += 8) {
            uint32_t afr[4][4];
            #pragma unroll
            for (int mi = 0; mi < 4; mi++) {
                const int r = m_w + mi * 16;
                afr[mi][0] = __float_as_uint(as[(r + group    ) * ROWF + ks + tig    ]);
                afr[mi][1] = __float_as_uint(as[(r + group + 8) * ROWF + ks + tig    ]);
                afr[mi][2] = __float_as_uint(as[(r + group    ) * ROWF + ks + tig + 4]);
                afr[mi][3] = __float_as_uint(as[(r + group + 8) * ROWF + ks + tig + 4]);
            }
            uint32_t bfr[8][2];
            #pragma unroll
            for (int ni = 0; ni < 8; ni++) {
                const int c = n_w + ni * 8;
                bfr[ni][0] = __float_as_uint(bs[(c + group) * ROWF + ks + tig    ]);
                bfr[ni][1] = __float_as_uint(bs[(c + group) * ROWF + ks + tig + 4]);
            }
            #pragma unroll
            for (int mi = 0; mi < 4; mi++)
                #pragma unroll
                for (int ni = 0; ni < 8; ni++)
                    mma_16x8x8(acc[mi][ni], afr[mi], bfr[ni]);
        }
        __syncthreads();
    }

    // ---- epilogue: coalesced float2 stores ----
    #pragma unroll
    for (int mi = 0; mi < 4; mi++) {
        const int row0 = bm + m_w + mi * 16 + group;
        #pragma unroll
        for (int ni = 0; ni < 8; ni++) {
            const int col0 = bn + n_w + ni * 8 + tig * 2;
            float v00 = acc[mi][ni][0] * alpha;
            float v01 = acc[mi][ni][1] * alpha;
            float v10 = acc[mi][ni][2] * alpha;
            float v11 = acc[mi][ni][3] * alpha;
            if (bias) {
                const float b0 = bias[col0], b1 = bias[col0 + 1];
                v00 += b0; v01 += b1; v10 += b0; v11 += b1;
            }
            if (ROUND_OUT) {
                v00 = tf32_round(v00); v01 = tf32_round(v01);
                v10 = tf32_round(v10); v11 = tf32_round(v11);
            }
            *reinterpret_cast<float2*>(&C[(size_t)row0 * ldc + col0]) =
                make_float2(v00, v01);
            *reinterpret_cast<float2*>(&C[(size_t)(row0 + 8) * ldc + col0]) =
                make_float2(v10, v11);
        }
    }
}

// ---------------------------------------------------------------------------
// Row softmax, in place, output rounded to tf32 (feeds the PV GEMM).
// One block (256 threads) per row of 2048 floats.
// ---------------------------------------------------------------------------
__global__ void __launch_bounds__(256)
softmax_kernel(float* __restrict__ Smat, int ncols)
{
    float* p = Smat + (size_t)blockIdx.x * ncols;
    const int tid  = threadIdx.x;
    const int warp = tid >> 5;
    const int lane = tid & 31;

    __shared__ float red_max[8];
    __shared__ float red_sum[8];

    float v[8];
    float mx = -1e30f;
    #pragma unroll
    for (int i = 0; i < 8; i++) {
        v[i] = p[tid + 256 * i];
        mx = fmaxf(mx, v[i]);
    }
    #pragma unroll
    for (int o = 16; o > 0; o >>= 1)
        mx = fmaxf(mx, __shfl_xor_sync(0xffffffffu, mx, o));
    if (lane == 0) red_max[warp] = mx;
    __syncthreads();
    float m = red_max[0];
    #pragma unroll
    for (int w = 1; w < 8; w++) m = fmaxf(m, red_max[w]);

    float sum = 0.f;
    #pragma unroll
    for (int i = 0; i < 8; i++) {
        v[i] = __expf(v[i] - m);
        sum += v[i];
    }
    #pragma unroll
    for (int o = 16; o > 0; o >>= 1)
        sum += __shfl_xor_sync(0xffffffffu, sum, o);
    if (lane == 0) red_sum[warp] = sum;
    __syncthreads();
    float total = 0.f;
    #pragma unroll
    for (int w = 0; w < 8; w++) total += red_sum[w];

    const float inv = 1.0f / total;
    #pragma unroll
    for (int i = 0; i < 8; i++)
        p[tid + 256 * i] = tf32_round(v[i] * inv);
}

// ---------------------------------------------------------------------------
extern "C" void kernel_launch(void* const* d_in, const int* in_sizes, int n_in,
                              void* d_out, int out_size)
{
    const float* x  = (const float*)d_in[0];
    const float* Wq = (const float*)d_in[1];
    const float* bq = (const float*)d_in[2];
    const float* Wk = (const float*)d_in[3];
    const float* bk = (const float*)d_in[4];
    const float* Wv = (const float*)d_in[5];
    const float* bv = (const float*)d_in[6];
    float* out = (float*)d_out;

    float *gqkv, *gvT, *gs, *gb;
    cudaGetSymbolAddress((void**)&gqkv, g_qkv);
    cudaGetSymbolAddress((void**)&gvT,  g_vT);
    cudaGetSymbolAddress((void**)&gs,   g_s);
    cudaGetSymbolAddress((void**)&gb,   g_b);

    // tf32-rounded copies of x and Wqkv, aliased into g_s (not yet live;
    // g_s is first written by the scores GEMM, which runs after QKV).
    float* xr = gs;                                    // 8192*1024
    float* wr = gs + (size_t)MQK * D;                  // 3*1024*1024, contiguous

    cudaFuncSetAttribute(gemm_mma_kernel<true>,
                         cudaFuncAttributeMaxDynamicSharedMemorySize, DYN_SMEM);
    cudaFuncSetAttribute(gemm_mma_kernel<false>,
                         cudaFuncAttributeMaxDynamicSharedMemorySize, DYN_SMEM);

    // 0) prep: round x + all weights (contiguous Wqkv), concat bias. One launch.
    prep_kernel<<<PREP_BLOCKS, 256>>>(x, Wq, Wk, Wv, bq, bk, bv, xr, wr, gb);

    const dim3 blk(128);

    // 1) fused QKV: [8192,3072] = xr @ Wqkv^T + b  (NT, rounded output)
    {
        const dim3 grid(N3 / BN, MQK / BM, 1);
        gemm_mma_kernel<true><<<grid, blk, DYN_SMEM>>>(
            xr, D, 0, wr, D, 0, gqkv, N3, 0, gb, D, 1.0f);
    }

    // 1b) transpose V block: g_vT[b][d][s] = qkv[b,s,2048+d]
    {
        const dim3 tgrid(S / 32, D / 32, Bsz);
        transpose_kernel<<<tgrid, 256>>>(gqkv, gvT);
    }

    // 2) scores[b] = Q[b] @ K[b]^T * (1/sqrt(D))  (Q,K are column blocks of qkv)
    {
        const dim3 grid(S / BN, S / BM, Bsz);
        gemm_mma_kernel<false><<<grid, blk, DYN_SMEM>>>(
            gqkv,     N3, (long long)S * N3,
            gqkv + D, N3, (long long)S * N3,
            gs, S, (long long)S * S,
            nullptr, D, 0.03125f /* 1/sqrt(1024) */);
    }

    // 3) row softmax (tf32-rounded output)
    softmax_kernel<<<Bsz * S, 256>>>(gs, S);

    // 4) out[b] = P[b] @ V[b] = P[b] @ (vT[b])^T  (NT path)
    {
        const dim3 grid(D / BN, S / BM, Bsz);
        gemm_mma_kernel<false><<<grid, blk, DYN_SMEM>>>(
            gs,  S, (long long)S * S,
            gvT, S, (long long)D * S,
            out, D, (long long)S * D,
            nullptr, S, 1.0f);
    }
}